// round 9
// baseline (speedup 1.0000x reference)
#include <cuda_runtime.h>
#include <math.h>

#define NU 100000
#define NI 50000
#define NT 10000
#define NNODES 160000
#define NE 800000
#define DD 64

typedef unsigned long long u64;

// ---------------- device scratch ----------------
__device__ float g_embsB[NNODES * DD];
__device__ float g_offB[NNODES * DD];
__device__ float g_EP[NNODES * 128];     // [0:64) eh=exp(h), [64:128) px=eh*x

__device__ int g_deg[NNODES];
__device__ int g_scan[NNODES];
__device__ int g_csr_off[NNODES + 1];
__device__ int g_pos[NNODES];
__device__ int g_csr_tail[NE];
__device__ int g_bsums[256];

// ---------------- packed f32x2 helpers ----------------
__device__ __forceinline__ u64 pack2(float a, float b) {
    u64 r; asm("mov.b64 %0,{%1,%2};" : "=l"(r) : "f"(a), "f"(b)); return r;
}
__device__ __forceinline__ float2 unpack2(u64 v) {
    float2 f; asm("mov.b64 {%0,%1},%2;" : "=f"(f.x), "=f"(f.y) : "l"(v)); return f;
}
__device__ __forceinline__ u64 ffma2(u64 a, u64 b, u64 c) {
    u64 d; asm("fma.rn.f32x2 %0,%1,%2,%3;" : "=l"(d) : "l"(a), "l"(b), "l"(c)); return d;
}

// ---------------- CSR build (multi-kernel, proven fastest) ----------------
__global__ void zero_deg_kernel() {
    int i = blockIdx.x * blockDim.x + threadIdx.x;
    if (i < NNODES) g_deg[i] = 0;
}

__global__ void hist_kernel(const int* __restrict__ head) {
    int e = blockIdx.x * blockDim.x + threadIdx.x;
    if (e < NE) atomicAdd(&g_deg[head[e]], 1);
}

#define SCAN_B 1024
__global__ void scan_block_kernel() {
    __shared__ int sh[SCAN_B];
    int g = blockIdx.x * SCAN_B + threadIdx.x;
    int v = (g < NNODES) ? g_deg[g] : 0;
    sh[threadIdx.x] = v;
    __syncthreads();
    for (int of = 1; of < SCAN_B; of <<= 1) {
        int t = (threadIdx.x >= of) ? sh[threadIdx.x - of] : 0;
        __syncthreads();
        sh[threadIdx.x] += t;
        __syncthreads();
    }
    if (g < NNODES) g_scan[g] = sh[threadIdx.x];
    if (threadIdx.x == SCAN_B - 1) g_bsums[blockIdx.x] = sh[threadIdx.x];
}

__global__ void scan_sums_kernel(int nb) {
    __shared__ int sh[256];
    int v = (threadIdx.x < nb) ? g_bsums[threadIdx.x] : 0;
    sh[threadIdx.x] = v;
    __syncthreads();
    for (int of = 1; of < 256; of <<= 1) {
        int t = (threadIdx.x >= of) ? sh[threadIdx.x - of] : 0;
        __syncthreads();
        sh[threadIdx.x] += t;
        __syncthreads();
    }
    if (threadIdx.x < nb) g_bsums[threadIdx.x] = sh[threadIdx.x] - v;  // exclusive
    if (threadIdx.x == 0) g_csr_off[0] = 0;
}

__global__ void scan_add_kernel() {
    int g = blockIdx.x * SCAN_B + threadIdx.x;
    if (g < NNODES) {
        int inc = g_scan[g] + g_bsums[blockIdx.x];
        g_csr_off[g + 1] = inc;
        g_pos[g] = inc - g_deg[g];
    }
}

__global__ void scatter_kernel(const int* __restrict__ head, const int* __restrict__ tail) {
    int e = blockIdx.x * blockDim.x + threadIdx.x;
    if (e < NE) {
        int h = head[e];
        int p = atomicAdd(&g_pos[h], 1);
        g_csr_tail[p] = tail[e];
    }
}

// ---------------- fused 2-stage MLP, low-LDS tiling ----------------
// 64x64 tile / block, 128 threads, 4 rows x 8 cols per thread.
// X transposed in smem (Xs[k][row], padded), W swizzled at 8-float granularity.
__device__ __forceinline__ int XS(int k, int r) {          // padded transpose index
    return k * 76 + r + ((r >> 4) << 2);
}
__device__ __forceinline__ int WSW(int k, int j) {         // 8-float xor swizzle
    return k * 64 + ((((j >> 3) ^ (k & 7)) << 3) | (j & 7));
}

template <int LAYER>
__global__ __launch_bounds__(128) void mlp_kernel(
    const float* __restrict__ ue, const float* __restrict__ ie, const float* __restrict__ te,
    const float* __restrict__ W1, const float* __restrict__ b1,
    const float* __restrict__ W2, const float* __restrict__ b2) {
    __shared__ float Ws[64 * 64];      // 16 KB
    __shared__ float Xs[64 * 76];      // 19 KB, transposed + padded

    int tid = threadIdx.x;
    int row0 = blockIdx.x * 64;

    // W1 transposed + swizzled (read coalesced over k)
    for (int i = tid; i < 4096; i += 128) {
        int j = i >> 6, k = i & 63;
        Ws[WSW(k, j)] = W1[i];
    }
    // X transposed into Xs[k][row]
    for (int i = tid; i < 1024; i += 128) {
        int rl = i >> 4, c4 = (i & 15) * 4;
        int row = row0 + rl;
        const float* src;
        if (LAYER == 0) {
            if (row < NU) src = ue + (size_t)row * 64;
            else if (row < NU + NI) src = ie + (size_t)(row - NU) * 64;
            else src = te + (size_t)(row - NU - NI) * 64;
        } else {
            src = g_embsB + (size_t)row * 64;
        }
        float4 v = *(const float4*)(src + c4);
        Xs[XS(c4 + 0, rl)] = v.x;
        Xs[XS(c4 + 1, rl)] = v.y;
        Xs[XS(c4 + 2, rl)] = v.z;
        Xs[XS(c4 + 3, rl)] = v.w;
    }
    __syncthreads();

    int tx = tid & 7, ty = tid >> 3;   // tx: col-group 0..7, ty: row-group 0..15
    int j0 = tx * 8, r0 = ty * 4;

    u64 acc[4][4];                     // [row][colpair]
    {
        float4 ba = *(const float4*)(b1 + j0);
        float4 bb = *(const float4*)(b1 + j0 + 4);
        u64 p0 = pack2(ba.x, ba.y), p1 = pack2(ba.z, ba.w);
        u64 p2 = pack2(bb.x, bb.y), p3 = pack2(bb.z, bb.w);
#pragma unroll
        for (int i = 0; i < 4; i++) { acc[i][0] = p0; acc[i][1] = p1; acc[i][2] = p2; acc[i][3] = p3; }
    }

#pragma unroll 8
    for (int k = 0; k < 64; k++) {
        int g = ((tx ^ (k & 7)) << 3);
        ulonglong2 wA = *(const ulonglong2*)&Ws[k * 64 + g];
        ulonglong2 wB = *(const ulonglong2*)&Ws[k * 64 + g + 4];
        float4 xv = *(const float4*)&Xs[XS(k, r0)];
        u64 x0 = pack2(xv.x, xv.x), x1 = pack2(xv.y, xv.y);
        u64 x2 = pack2(xv.z, xv.z), x3 = pack2(xv.w, xv.w);
        acc[0][0] = ffma2(x0, wA.x, acc[0][0]); acc[0][1] = ffma2(x0, wA.y, acc[0][1]);
        acc[0][2] = ffma2(x0, wB.x, acc[0][2]); acc[0][3] = ffma2(x0, wB.y, acc[0][3]);
        acc[1][0] = ffma2(x1, wA.x, acc[1][0]); acc[1][1] = ffma2(x1, wA.y, acc[1][1]);
        acc[1][2] = ffma2(x1, wB.x, acc[1][2]); acc[1][3] = ffma2(x1, wB.y, acc[1][3]);
        acc[2][0] = ffma2(x2, wA.x, acc[2][0]); acc[2][1] = ffma2(x2, wA.y, acc[2][1]);
        acc[2][2] = ffma2(x2, wB.x, acc[2][2]); acc[2][3] = ffma2(x2, wB.y, acc[2][3]);
        acc[3][0] = ffma2(x3, wA.x, acc[3][0]); acc[3][1] = ffma2(x3, wA.y, acc[3][1]);
        acc[3][2] = ffma2(x3, wB.x, acc[3][2]); acc[3][3] = ffma2(x3, wB.y, acc[3][3]);
    }
    __syncthreads();

    // h = relu(acc) -> Xs transposed (Xs[col][row]); reload Ws with W2
#pragma unroll
    for (int p = 0; p < 4; p++) {
        float2 h0 = unpack2(acc[0][p]);
        float2 h1 = unpack2(acc[1][p]);
        float2 h2 = unpack2(acc[2][p]);
        float2 h3 = unpack2(acc[3][p]);
        float4 colA = make_float4(fmaxf(h0.x, 0.f), fmaxf(h1.x, 0.f), fmaxf(h2.x, 0.f), fmaxf(h3.x, 0.f));
        float4 colB = make_float4(fmaxf(h0.y, 0.f), fmaxf(h1.y, 0.f), fmaxf(h2.y, 0.f), fmaxf(h3.y, 0.f));
        *(float4*)&Xs[XS(j0 + 2 * p + 0, r0)] = colA;
        *(float4*)&Xs[XS(j0 + 2 * p + 1, r0)] = colB;
    }
    for (int i = tid; i < 4096; i += 128) {
        int j = i >> 6, k = i & 63;
        Ws[WSW(k, j)] = W2[i];
    }
    __syncthreads();

    {
        float4 ba = *(const float4*)(b2 + j0);
        float4 bb = *(const float4*)(b2 + j0 + 4);
        u64 p0 = pack2(ba.x, ba.y), p1 = pack2(ba.z, ba.w);
        u64 p2 = pack2(bb.x, bb.y), p3 = pack2(bb.z, bb.w);
#pragma unroll
        for (int i = 0; i < 4; i++) { acc[i][0] = p0; acc[i][1] = p1; acc[i][2] = p2; acc[i][3] = p3; }
    }

#pragma unroll 8
    for (int k = 0; k < 64; k++) {
        int g = ((tx ^ (k & 7)) << 3);
        ulonglong2 wA = *(const ulonglong2*)&Ws[k * 64 + g];
        ulonglong2 wB = *(const ulonglong2*)&Ws[k * 64 + g + 4];
        float4 xv = *(const float4*)&Xs[XS(k, r0)];
        u64 x0 = pack2(xv.x, xv.x), x1 = pack2(xv.y, xv.y);
        u64 x2 = pack2(xv.z, xv.z), x3 = pack2(xv.w, xv.w);
        acc[0][0] = ffma2(x0, wA.x, acc[0][0]); acc[0][1] = ffma2(x0, wA.y, acc[0][1]);
        acc[0][2] = ffma2(x0, wB.x, acc[0][2]); acc[0][3] = ffma2(x0, wB.y, acc[0][3]);
        acc[1][0] = ffma2(x1, wA.x, acc[1][0]); acc[1][1] = ffma2(x1, wA.y, acc[1][1]);
        acc[1][2] = ffma2(x1, wB.x, acc[1][2]); acc[1][3] = ffma2(x1, wB.y, acc[1][3]);
        acc[2][0] = ffma2(x2, wA.x, acc[2][0]); acc[2][1] = ffma2(x2, wA.y, acc[2][1]);
        acc[2][2] = ffma2(x2, wB.x, acc[2][2]); acc[2][3] = ffma2(x2, wB.y, acc[2][3]);
        acc[3][0] = ffma2(x3, wA.x, acc[3][0]); acc[3][1] = ffma2(x3, wA.y, acc[3][1]);
        acc[3][2] = ffma2(x3, wB.x, acc[3][2]); acc[3][3] = ffma2(x3, wB.y, acc[3][3]);
    }

    // epilogue: eh = exp(y), px = eh * x  (8 cols per row)
#pragma unroll
    for (int i = 0; i < 4; i++) {
        int row = row0 + r0 + i;
        const float* src;
        if (LAYER == 0) {
            if (row < NU) src = ue + (size_t)row * 64;
            else if (row < NU + NI) src = ie + (size_t)(row - NU) * 64;
            else src = te + (size_t)(row - NU - NI) * 64;
        } else {
            src = g_embsB + (size_t)row * 64;
        }
        float4 xa = *(const float4*)(src + j0);
        float4 xb = *(const float4*)(src + j0 + 4);
        float2 u0 = unpack2(acc[i][0]);
        float2 u1 = unpack2(acc[i][1]);
        float2 u2 = unpack2(acc[i][2]);
        float2 u3 = unpack2(acc[i][3]);
        float e0 = __expf(u0.x), e1 = __expf(u0.y), e2 = __expf(u1.x), e3 = __expf(u1.y);
        float e4 = __expf(u2.x), e5 = __expf(u2.y), e6 = __expf(u3.x), e7 = __expf(u3.y);
        size_t base = (size_t)row * 128;
        *(float4*)&g_EP[base + j0]          = make_float4(e0, e1, e2, e3);
        *(float4*)&g_EP[base + j0 + 4]      = make_float4(e4, e5, e6, e7);
        *(float4*)&g_EP[base + 64 + j0]     = make_float4(e0 * xa.x, e1 * xa.y, e2 * xa.z, e3 * xa.w);
        *(float4*)&g_EP[base + 64 + j0 + 4] = make_float4(e4 * xb.x, e5 * xb.y, e6 * xb.z, e7 * xb.w);
    }
}

// ---------------- per-node aggregation (proven R5/R8 shape) ----------------
template <int FINAL>
__global__ __launch_bounds__(256) void aggregate_kernel(
    const float* __restrict__ uo, const float* __restrict__ io, const float* __restrict__ to,
    float* __restrict__ out) {
    int w = (blockIdx.x * blockDim.x + threadIdx.x) >> 5;
    if (w >= NNODES) return;
    int lane = threadIdx.x & 31;
    int half = lane >> 4;
    int fl = (lane & 15) * 4;

    int beg = g_csr_off[w];
    int end = g_csr_off[w + 1];
    const bool is_user = (w < NU);
    const bool is_item = (w >= NU) && (w < NU + NI);

    float4 s = make_float4(0.f, 0.f, 0.f, 0.f);
    float4 n = make_float4(0.f, 0.f, 0.f, 0.f);
    float4 mn = make_float4(INFINITY, INFINITY, INFINITY, INFINITY);
    float4 mx = make_float4(0.f, 0.f, 0.f, 0.f);

    for (int chunk = beg; chunk < end; chunk += 32) {
        int nn = end - chunk; if (nn > 32) nn = 32;
        int tl = 0;
        if (lane < nn) tl = __ldg(&g_csr_tail[chunk + lane]);
#pragma unroll 4
        for (int q = 0; q < nn; q += 2) {
            int idx = q + half;
            int t = __shfl_sync(0xffffffffu, tl, idx & 31);
            if (idx < nn) {
                size_t epb = (size_t)t * 128;
                float4 eh = __ldg((const float4*)&g_EP[epb + fl]);
                float4 px = __ldg((const float4*)&g_EP[epb + 64 + fl]);

                s.x += eh.x; s.y += eh.y; s.z += eh.z; s.w += eh.w;
                n.x += px.x; n.y += px.y; n.z += px.z; n.w += px.w;

                bool need_off = !(is_user && t < NU);
                if (need_off) {
                    const float* op;
                    if (FINAL == 0) {
                        if (t < NU)           op = uo + (size_t)t * 64;
                        else if (t < NU + NI) op = io + (size_t)(t - NU) * 64;
                        else                  op = to + (size_t)(t - NU - NI) * 64;
                    } else {
                        op = g_offB + (size_t)t * 64;
                    }
                    float4 o = __ldg((const float4*)(op + fl));
                    if (FINAL == 0) {
                        o.x = fmaxf(o.x, 0.f); o.y = fmaxf(o.y, 0.f);
                        o.z = fmaxf(o.z, 0.f); o.w = fmaxf(o.w, 0.f);
                    }
                    bool t_item = (t >= NU) && (t < NU + NI);
                    bool t_tag  = (t >= NU + NI);
                    bool do_min = is_user ? t_item : (!is_item);
                    bool do_max = is_user ? t_tag  : is_item;
                    if (do_min) {
                        mn.x = fminf(mn.x, o.x); mn.y = fminf(mn.y, o.y);
                        mn.z = fminf(mn.z, o.z); mn.w = fminf(mn.w, o.w);
                    }
                    if (do_max) {
                        mx.x = fmaxf(mx.x, o.x); mx.y = fmaxf(mx.y, o.y);
                        mx.z = fmaxf(mx.z, o.z); mx.w = fmaxf(mx.w, o.w);
                    }
                }
            }
        }
    }

#define MRG_ADD(v) v += __shfl_xor_sync(0xffffffffu, v, 16)
#define MRG_MIN(v) v = fminf(v, __shfl_xor_sync(0xffffffffu, v, 16))
#define MRG_MAX(v) v = fmaxf(v, __shfl_xor_sync(0xffffffffu, v, 16))
    MRG_ADD(s.x); MRG_ADD(s.y); MRG_ADD(s.z); MRG_ADD(s.w);
    MRG_ADD(n.x); MRG_ADD(n.y); MRG_ADD(n.z); MRG_ADD(n.w);
    MRG_MIN(mn.x); MRG_MIN(mn.y); MRG_MIN(mn.z); MRG_MIN(mn.w);
    MRG_MAX(mx.x); MRG_MAX(mx.y); MRG_MAX(mx.z); MRG_MAX(mx.w);

    float4 a;
    a.x = (s.x > 0.f) ? n.x / s.x : 0.f;
    a.y = (s.y > 0.f) ? n.y / s.y : 0.f;
    a.z = (s.z > 0.f) ? n.z / s.z : 0.f;
    a.w = (s.w > 0.f) ? n.w / s.w : 0.f;

    float ss = a.x * a.x + a.y * a.y + a.z * a.z + a.w * a.w;
#pragma unroll
    for (int of = 8; of; of >>= 1) ss += __shfl_xor_sync(0xffffffffu, ss, of);
    float inv = 1.f / fmaxf(sqrtf(ss), 1e-12f);
    a.x *= inv; a.y *= inv; a.z *= inv; a.w *= inv;

    float4 ov;
    if (is_user) {
        float i0 = isinf(mn.x) ? 0.f : mn.x;
        float i1 = isinf(mn.y) ? 0.f : mn.y;
        float i2 = isinf(mn.z) ? 0.f : mn.z;
        float i3 = isinf(mn.w) ? 0.f : mn.w;
        ov = make_float4(fminf(i0, mx.x), fminf(i1, mx.y), fminf(i2, mx.z), fminf(i3, mx.w));
    } else if (is_item) {
        ov = mx;
    } else {
        ov.x = isinf(mn.x) ? 0.f : mn.x;
        ov.y = isinf(mn.y) ? 0.f : mn.y;
        ov.z = isinf(mn.z) ? 0.f : mn.z;
        ov.w = isinf(mn.w) ? 0.f : mn.w;
    }
    ov.x = fmaxf(ov.x, 0.f); ov.y = fmaxf(ov.y, 0.f);
    ov.z = fmaxf(ov.z, 0.f); ov.w = fmaxf(ov.w, 0.f);

    if (FINAL == 0) {
        size_t base = (size_t)w * 64 + fl;
        if (half == 0) *(float4*)(g_embsB + base) = a;
        else           *(float4*)(g_offB + base)  = ov;
    } else {
        size_t eb, ob;
        if (is_user) {
            eb = (size_t)w * 64;
            ob = (size_t)NU * 64 + (size_t)w * 64;
        } else if (is_item) {
            size_t b2 = (size_t)2 * NU * 64;
            eb = b2 + (size_t)(w - NU) * 64;
            ob = b2 + (size_t)NI * 64 + (size_t)(w - NU) * 64;
        } else {
            size_t b3 = (size_t)2 * (NU + NI) * 64;
            eb = b3 + (size_t)(w - NU - NI) * 64;
            ob = b3 + (size_t)NT * 64 + (size_t)(w - NU - NI) * 64;
        }
        if (half == 0) *(float4*)(out + eb + fl) = a;
        else           *(float4*)(out + ob + fl) = ov;
    }
}

// ---------------- launch ----------------
extern "C" void kernel_launch(void* const* d_in, const int* in_sizes, int n_in,
                              void* d_out, int out_size) {
    const float* user_emb = (const float*)d_in[0];
    const float* user_off = (const float*)d_in[1];
    const float* item_emb = (const float*)d_in[2];
    const float* item_off = (const float*)d_in[3];
    const float* tag_emb  = (const float*)d_in[4];
    const float* tag_off  = (const float*)d_in[5];
    const float* W1 = (const float*)d_in[6];
    const float* b1 = (const float*)d_in[7];
    const float* W2 = (const float*)d_in[8];
    const float* b2 = (const float*)d_in[9];
    const int* head = (const int*)d_in[10];
    const int* tail = (const int*)d_in[11];
    float* out = (float*)d_out;

    const int NB = (NNODES + SCAN_B - 1) / SCAN_B;

    // slot #4 (ncu capture) = mlp<0>; CSR chain completes before aggregate<0>
    zero_deg_kernel<<<(NNODES + 255) / 256, 256>>>(); // 1
    hist_kernel<<<(NE + 255) / 256, 256>>>(head);     // 2
    scan_block_kernel<<<NB, SCAN_B>>>();              // 3
    mlp_kernel<0><<<NNODES / 64, 128>>>(user_emb, item_emb, tag_emb,
                                        W1, b1, W2, b2);  // 4 <- profiled
    scan_sums_kernel<<<1, 256>>>(NB);                 // 5
    scan_add_kernel<<<NB, SCAN_B>>>();                // 6
    scatter_kernel<<<(NE + 255) / 256, 256>>>(head, tail);  // 7
    aggregate_kernel<0><<<(NNODES + 7) / 8, 256>>>(
        user_off, item_off, tag_off, out);            // 8
    mlp_kernel<1><<<NNODES / 64, 128>>>(user_emb, item_emb, tag_emb,
                                        W1, b1, W2, b2);  // 9
    aggregate_kernel<1><<<(NNODES + 7) / 8, 256>>>(
        user_off, item_off, tag_off, out);            // 10
}

// round 10
// speedup vs baseline: 1.1176x; 1.1176x over previous
#include <cuda_runtime.h>
#include <math.h>

#define NU 100000
#define NI 50000
#define NT 10000
#define NNODES 160000
#define NE 800000
#define DD 64

typedef unsigned long long u64;

// ---------------- device scratch ----------------
__device__ float g_embsB[NNODES * DD];
__device__ float g_offB[NNODES * DD];
__device__ float g_EP[NNODES * 128];     // [0:64) eh=exp(h), [64:128) px=eh*x

__device__ int g_deg[NNODES];
__device__ int g_scan[NNODES];
__device__ int g_csr_off[NNODES + 1];
__device__ int g_pos[NNODES];
__device__ int g_csr_tail[NE];
__device__ int g_bsums[256];

// ---------------- packed f32x2 helpers ----------------
__device__ __forceinline__ u64 pack2(float a, float b) {
    u64 r; asm("mov.b64 %0,{%1,%2};" : "=l"(r) : "f"(a), "f"(b)); return r;
}
__device__ __forceinline__ u64 dup2(float a) {
    u64 r; asm("mov.b64 %0,{%1,%1};" : "=l"(r) : "f"(a)); return r;
}
__device__ __forceinline__ float2 unpack2(u64 v) {
    float2 f; asm("mov.b64 {%0,%1},%2;" : "=f"(f.x), "=f"(f.y) : "l"(v)); return f;
}
__device__ __forceinline__ u64 ffma2(u64 a, u64 b, u64 c) {
    u64 d; asm("fma.rn.f32x2 %0,%1,%2,%3;" : "=l"(d) : "l"(a), "l"(b), "l"(c)); return d;
}

// ---------------- CSR build (multi-kernel, proven fastest) ----------------
__global__ void zero_deg_kernel() {
    int i = blockIdx.x * blockDim.x + threadIdx.x;
    if (i < NNODES) g_deg[i] = 0;
}

__global__ void hist_kernel(const int* __restrict__ head) {
    int e = blockIdx.x * blockDim.x + threadIdx.x;
    if (e < NE) atomicAdd(&g_deg[head[e]], 1);
}

#define SCAN_B 1024
__global__ void scan_block_kernel() {
    __shared__ int sh[SCAN_B];
    int g = blockIdx.x * SCAN_B + threadIdx.x;
    int v = (g < NNODES) ? g_deg[g] : 0;
    sh[threadIdx.x] = v;
    __syncthreads();
    for (int of = 1; of < SCAN_B; of <<= 1) {
        int t = (threadIdx.x >= of) ? sh[threadIdx.x - of] : 0;
        __syncthreads();
        sh[threadIdx.x] += t;
        __syncthreads();
    }
    if (g < NNODES) g_scan[g] = sh[threadIdx.x];
    if (threadIdx.x == SCAN_B - 1) g_bsums[blockIdx.x] = sh[threadIdx.x];
}

__global__ void scan_sums_kernel(int nb) {
    __shared__ int sh[256];
    int v = (threadIdx.x < nb) ? g_bsums[threadIdx.x] : 0;
    sh[threadIdx.x] = v;
    __syncthreads();
    for (int of = 1; of < 256; of <<= 1) {
        int t = (threadIdx.x >= of) ? sh[threadIdx.x - of] : 0;
        __syncthreads();
        sh[threadIdx.x] += t;
        __syncthreads();
    }
    if (threadIdx.x < nb) g_bsums[threadIdx.x] = sh[threadIdx.x] - v;
    if (threadIdx.x == 0) g_csr_off[0] = 0;
}

__global__ void scan_add_kernel() {
    int g = blockIdx.x * SCAN_B + threadIdx.x;
    if (g < NNODES) {
        int inc = g_scan[g] + g_bsums[blockIdx.x];
        g_csr_off[g + 1] = inc;
        g_pos[g] = inc - g_deg[g];
    }
}

__global__ void scatter_kernel(const int* __restrict__ head, const int* __restrict__ tail) {
    int e = blockIdx.x * blockDim.x + threadIdx.x;
    if (e < NE) {
        int h = head[e];
        int p = atomicAdd(&g_pos[h], 1);
        g_csr_tail[p] = tail[e];
    }
}

// ---------------- MLP v3: row-pair FFMA2, 128 thr, tile 128x64, thread 8x8 ----------------
// Xs transposed: col k, row r stored at Xs[k*128 + (r ^ (8*((k>>3)&3)))]
// Ws chunk layout: 16B chunk m=j>>2 at float offset ((m&1)<<5) + ((m>>1)<<2)
__device__ __forceinline__ int xswz(int k, int r) {
    return k * 128 + (r ^ ((k >> 3 & 3) << 3));
}
__device__ __forceinline__ int wpos(int k, int j) {
    int m = j >> 2;
    return k * 64 + ((m & 1) << 5) + ((m >> 1) << 2) + (j & 3);
}

template <int LAYER>
__global__ __launch_bounds__(128) void mlp_kernel(
    const float* __restrict__ ue, const float* __restrict__ ie, const float* __restrict__ te,
    const float* __restrict__ W1, const float* __restrict__ b1,
    const float* __restrict__ W2, const float* __restrict__ b2) {
    __shared__ __align__(16) float Ws[64 * 64];    // 16 KB
    __shared__ __align__(16) float Xs[64 * 128];   // 32 KB

    const int tid = threadIdx.x;
    const int row0 = blockIdx.x * 128;

    // W1[j][k] -> Ws (chunk-permuted), coalesced over k
    for (int i = tid; i < 4096; i += 128) {
        int j = i >> 6, k = i & 63;
        Ws[wpos(k, j)] = W1[i];
    }
    // X transposed into Xs (swizzled rows)
    for (int i = tid; i < 2048; i += 128) {
        int rl = i >> 4, c4 = (i & 15) * 4;
        int row = row0 + rl;
        const float* src;
        if (LAYER == 0) {
            if (row < NU) src = ue + (size_t)row * 64;
            else if (row < NU + NI) src = ie + (size_t)(row - NU) * 64;
            else src = te + (size_t)(row - NU - NI) * 64;
        } else {
            src = g_embsB + (size_t)row * 64;
        }
        float4 v = *(const float4*)(src + c4);
        Xs[xswz(c4 + 0, rl)] = v.x;
        Xs[xswz(c4 + 1, rl)] = v.y;
        Xs[xswz(c4 + 2, rl)] = v.z;
        Xs[xswz(c4 + 3, rl)] = v.w;
    }
    __syncthreads();

    const int tx = tid & 7, ty = tid >> 3;   // tx: col-group 0..7, ty: row-group 0..15
    const int j0 = tx * 8, r0 = ty * 8;

    u64 acc[4][8];   // [rowpair][col]; pair i covers rows (r0+2i, r0+2i+1)
    {
        float4 ba = *(const float4*)(b1 + j0);
        float4 bb = *(const float4*)(b1 + j0 + 4);
        u64 d0 = dup2(ba.x), d1 = dup2(ba.y), d2 = dup2(ba.z), d3 = dup2(ba.w);
        u64 d4 = dup2(bb.x), d5 = dup2(bb.y), d6 = dup2(bb.z), d7 = dup2(bb.w);
#pragma unroll
        for (int i = 0; i < 4; i++) {
            acc[i][0] = d0; acc[i][1] = d1; acc[i][2] = d2; acc[i][3] = d3;
            acc[i][4] = d4; acc[i][5] = d5; acc[i][6] = d6; acc[i][7] = d7;
        }
    }

#pragma unroll 8
    for (int k = 0; k < 64; k++) {
        int xb = k * 128 + (r0 ^ ((k >> 3 & 3) << 3));
        ulonglong2 xA = *(const ulonglong2*)&Xs[xb];       // rows r0..r0+3 (2 pairs)
        ulonglong2 xB = *(const ulonglong2*)&Xs[xb + 4];   // rows r0+4..r0+7
        float4 wa = *(const float4*)&Ws[k * 64 + tx * 4];        // cols j0..j0+3
        float4 wb = *(const float4*)&Ws[k * 64 + 32 + tx * 4];   // cols j0+4..j0+7
        u64 w0 = dup2(wa.x), w1 = dup2(wa.y), w2 = dup2(wa.z), w3 = dup2(wa.w);
        u64 w4 = dup2(wb.x), w5 = dup2(wb.y), w6 = dup2(wb.z), w7 = dup2(wb.w);
        acc[0][0] = ffma2(xA.x, w0, acc[0][0]); acc[0][1] = ffma2(xA.x, w1, acc[0][1]);
        acc[0][2] = ffma2(xA.x, w2, acc[0][2]); acc[0][3] = ffma2(xA.x, w3, acc[0][3]);
        acc[0][4] = ffma2(xA.x, w4, acc[0][4]); acc[0][5] = ffma2(xA.x, w5, acc[0][5]);
        acc[0][6] = ffma2(xA.x, w6, acc[0][6]); acc[0][7] = ffma2(xA.x, w7, acc[0][7]);
        acc[1][0] = ffma2(xA.y, w0, acc[1][0]); acc[1][1] = ffma2(xA.y, w1, acc[1][1]);
        acc[1][2] = ffma2(xA.y, w2, acc[1][2]); acc[1][3] = ffma2(xA.y, w3, acc[1][3]);
        acc[1][4] = ffma2(xA.y, w4, acc[1][4]); acc[1][5] = ffma2(xA.y, w5, acc[1][5]);
        acc[1][6] = ffma2(xA.y, w6, acc[1][6]); acc[1][7] = ffma2(xA.y, w7, acc[1][7]);
        acc[2][0] = ffma2(xB.x, w0, acc[2][0]); acc[2][1] = ffma2(xB.x, w1, acc[2][1]);
        acc[2][2] = ffma2(xB.x, w2, acc[2][2]); acc[2][3] = ffma2(xB.x, w3, acc[2][3]);
        acc[2][4] = ffma2(xB.x, w4, acc[2][4]); acc[2][5] = ffma2(xB.x, w5, acc[2][5]);
        acc[2][6] = ffma2(xB.x, w6, acc[2][6]); acc[2][7] = ffma2(xB.x, w7, acc[2][7]);
        acc[3][0] = ffma2(xB.y, w0, acc[3][0]); acc[3][1] = ffma2(xB.y, w1, acc[3][1]);
        acc[3][2] = ffma2(xB.y, w2, acc[3][2]); acc[3][3] = ffma2(xB.y, w3, acc[3][3]);
        acc[3][4] = ffma2(xB.y, w4, acc[3][4]); acc[3][5] = ffma2(xB.y, w5, acc[3][5]);
        acc[3][6] = ffma2(xB.y, w6, acc[3][6]); acc[3][7] = ffma2(xB.y, w7, acc[3][7]);
    }
    __syncthreads();   // all Xs/Ws reads done before overwrite

    // h = relu(acc) stored transposed into Xs (thread owns cols j0..j0+7, rows r0..r0+7)
    {
        int mj = (tx & 3) << 3;
#pragma unroll
        for (int c = 0; c < 8; c++) {
            int j = j0 + c;
            u64 h[4];
#pragma unroll
            for (int i = 0; i < 4; i++) {
                float2 p = unpack2(acc[i][c]);
                h[i] = pack2(fmaxf(p.x, 0.f), fmaxf(p.y, 0.f));
            }
            ulonglong2 hA; hA.x = h[0]; hA.y = h[1];
            ulonglong2 hB; hB.x = h[2]; hB.y = h[3];
            int base = j * 128 + (r0 ^ mj);
            *(ulonglong2*)&Xs[base] = hA;
            *(ulonglong2*)&Xs[base + 4] = hB;
        }
    }
    for (int i = tid; i < 4096; i += 128) {
        int j = i >> 6, k = i & 63;
        Ws[wpos(k, j)] = W2[i];
    }
    __syncthreads();

    {
        float4 ba = *(const float4*)(b2 + j0);
        float4 bb = *(const float4*)(b2 + j0 + 4);
        u64 d0 = dup2(ba.x), d1 = dup2(ba.y), d2 = dup2(ba.z), d3 = dup2(ba.w);
        u64 d4 = dup2(bb.x), d5 = dup2(bb.y), d6 = dup2(bb.z), d7 = dup2(bb.w);
#pragma unroll
        for (int i = 0; i < 4; i++) {
            acc[i][0] = d0; acc[i][1] = d1; acc[i][2] = d2; acc[i][3] = d3;
            acc[i][4] = d4; acc[i][5] = d5; acc[i][6] = d6; acc[i][7] = d7;
        }
    }

#pragma unroll 8
    for (int k = 0; k < 64; k++) {
        int xb = k * 128 + (r0 ^ ((k >> 3 & 3) << 3));
        ulonglong2 xA = *(const ulonglong2*)&Xs[xb];
        ulonglong2 xB = *(const ulonglong2*)&Xs[xb + 4];
        float4 wa = *(const float4*)&Ws[k * 64 + tx * 4];
        float4 wb = *(const float4*)&Ws[k * 64 + 32 + tx * 4];
        u64 w0 = dup2(wa.x), w1 = dup2(wa.y), w2 = dup2(wa.z), w3 = dup2(wa.w);
        u64 w4 = dup2(wb.x), w5 = dup2(wb.y), w6 = dup2(wb.z), w7 = dup2(wb.w);
        acc[0][0] = ffma2(xA.x, w0, acc[0][0]); acc[0][1] = ffma2(xA.x, w1, acc[0][1]);
        acc[0][2] = ffma2(xA.x, w2, acc[0][2]); acc[0][3] = ffma2(xA.x, w3, acc[0][3]);
        acc[0][4] = ffma2(xA.x, w4, acc[0][4]); acc[0][5] = ffma2(xA.x, w5, acc[0][5]);
        acc[0][6] = ffma2(xA.x, w6, acc[0][6]); acc[0][7] = ffma2(xA.x, w7, acc[0][7]);
        acc[1][0] = ffma2(xA.y, w0, acc[1][0]); acc[1][1] = ffma2(xA.y, w1, acc[1][1]);
        acc[1][2] = ffma2(xA.y, w2, acc[1][2]); acc[1][3] = ffma2(xA.y, w3, acc[1][3]);
        acc[1][4] = ffma2(xA.y, w4, acc[1][4]); acc[1][5] = ffma2(xA.y, w5, acc[1][5]);
        acc[1][6] = ffma2(xA.y, w6, acc[1][6]); acc[1][7] = ffma2(xA.y, w7, acc[1][7]);
        acc[2][0] = ffma2(xB.x, w0, acc[2][0]); acc[2][1] = ffma2(xB.x, w1, acc[2][1]);
        acc[2][2] = ffma2(xB.x, w2, acc[2][2]); acc[2][3] = ffma2(xB.x, w3, acc[2][3]);
        acc[2][4] = ffma2(xB.x, w4, acc[2][4]); acc[2][5] = ffma2(xB.x, w5, acc[2][5]);
        acc[2][6] = ffma2(xB.x, w6, acc[2][6]); acc[2][7] = ffma2(xB.x, w7, acc[2][7]);
        acc[3][0] = ffma2(xB.y, w0, acc[3][0]); acc[3][1] = ffma2(xB.y, w1, acc[3][1]);
        acc[3][2] = ffma2(xB.y, w2, acc[3][2]); acc[3][3] = ffma2(xB.y, w3, acc[3][3]);
        acc[3][4] = ffma2(xB.y, w4, acc[3][4]); acc[3][5] = ffma2(xB.y, w5, acc[3][5]);
        acc[3][6] = ffma2(xB.y, w6, acc[3][6]); acc[3][7] = ffma2(xB.y, w7, acc[3][7]);
    }

    // epilogue: per pair i -> rows r0+2i, r0+2i+1; eh=exp(y), px=eh*x
#pragma unroll
    for (int i = 0; i < 4; i++) {
        float2 u[8];
#pragma unroll
        for (int c = 0; c < 8; c++) u[c] = unpack2(acc[i][c]);
#pragma unroll
        for (int half = 0; half < 2; half++) {
            int row = row0 + r0 + 2 * i + half;
            const float* src;
            if (LAYER == 0) {
                if (row < NU) src = ue + (size_t)row * 64;
                else if (row < NU + NI) src = ie + (size_t)(row - NU) * 64;
                else src = te + (size_t)(row - NU - NI) * 64;
            } else {
                src = g_embsB + (size_t)row * 64;
            }
            float4 xa = *(const float4*)(src + j0);
            float4 xb = *(const float4*)(src + j0 + 4);
            float y0 = half ? u[0].y : u[0].x;
            float y1 = half ? u[1].y : u[1].x;
            float y2 = half ? u[2].y : u[2].x;
            float y3 = half ? u[3].y : u[3].x;
            float y4 = half ? u[4].y : u[4].x;
            float y5 = half ? u[5].y : u[5].x;
            float y6 = half ? u[6].y : u[6].x;
            float y7 = half ? u[7].y : u[7].x;
            float e0 = __expf(y0), e1 = __expf(y1), e2 = __expf(y2), e3 = __expf(y3);
            float e4 = __expf(y4), e5 = __expf(y5), e6 = __expf(y6), e7 = __expf(y7);
            size_t base = (size_t)row * 128;
            *(float4*)&g_EP[base + j0]          = make_float4(e0, e1, e2, e3);
            *(float4*)&g_EP[base + j0 + 4]      = make_float4(e4, e5, e6, e7);
            *(float4*)&g_EP[base + 64 + j0]     = make_float4(e0 * xa.x, e1 * xa.y, e2 * xa.z, e3 * xa.w);
            *(float4*)&g_EP[base + 64 + j0 + 4] = make_float4(e4 * xb.x, e5 * xb.y, e6 * xb.z, e7 * xb.w);
        }
    }
}

// ---------------- per-node aggregation (proven R5/R8 shape) ----------------
template <int FINAL>
__global__ __launch_bounds__(256) void aggregate_kernel(
    const float* __restrict__ uo, const float* __restrict__ io, const float* __restrict__ to,
    float* __restrict__ out) {
    int w = (blockIdx.x * blockDim.x + threadIdx.x) >> 5;
    if (w >= NNODES) return;
    int lane = threadIdx.x & 31;
    int half = lane >> 4;
    int fl = (lane & 15) * 4;

    int beg = g_csr_off[w];
    int end = g_csr_off[w + 1];
    const bool is_user = (w < NU);
    const bool is_item = (w >= NU) && (w < NU + NI);

    float4 s = make_float4(0.f, 0.f, 0.f, 0.f);
    float4 n = make_float4(0.f, 0.f, 0.f, 0.f);
    float4 mn = make_float4(INFINITY, INFINITY, INFINITY, INFINITY);
    float4 mx = make_float4(0.f, 0.f, 0.f, 0.f);

    for (int chunk = beg; chunk < end; chunk += 32) {
        int nn = end - chunk; if (nn > 32) nn = 32;
        int tl = 0;
        if (lane < nn) tl = __ldg(&g_csr_tail[chunk + lane]);
#pragma unroll 4
        for (int q = 0; q < nn; q += 2) {
            int idx = q + half;
            int t = __shfl_sync(0xffffffffu, tl, idx & 31);
            if (idx < nn) {
                size_t epb = (size_t)t * 128;
                float4 eh = __ldg((const float4*)&g_EP[epb + fl]);
                float4 px = __ldg((const float4*)&g_EP[epb + 64 + fl]);

                s.x += eh.x; s.y += eh.y; s.z += eh.z; s.w += eh.w;
                n.x += px.x; n.y += px.y; n.z += px.z; n.w += px.w;

                bool need_off = !(is_user && t < NU);
                if (need_off) {
                    const float* op;
                    if (FINAL == 0) {
                        if (t < NU)           op = uo + (size_t)t * 64;
                        else if (t < NU + NI) op = io + (size_t)(t - NU) * 64;
                        else                  op = to + (size_t)(t - NU - NI) * 64;
                    } else {
                        op = g_offB + (size_t)t * 64;
                    }
                    float4 o = __ldg((const float4*)(op + fl));
                    if (FINAL == 0) {
                        o.x = fmaxf(o.x, 0.f); o.y = fmaxf(o.y, 0.f);
                        o.z = fmaxf(o.z, 0.f); o.w = fmaxf(o.w, 0.f);
                    }
                    bool t_item = (t >= NU) && (t < NU + NI);
                    bool t_tag  = (t >= NU + NI);
                    bool do_min = is_user ? t_item : (!is_item);
                    bool do_max = is_user ? t_tag  : is_item;
                    if (do_min) {
                        mn.x = fminf(mn.x, o.x); mn.y = fminf(mn.y, o.y);
                        mn.z = fminf(mn.z, o.z); mn.w = fminf(mn.w, o.w);
                    }
                    if (do_max) {
                        mx.x = fmaxf(mx.x, o.x); mx.y = fmaxf(mx.y, o.y);
                        mx.z = fmaxf(mx.z, o.z); mx.w = fmaxf(mx.w, o.w);
                    }
                }
            }
        }
    }

#define MRG_ADD(v) v += __shfl_xor_sync(0xffffffffu, v, 16)
#define MRG_MIN(v) v = fminf(v, __shfl_xor_sync(0xffffffffu, v, 16))
#define MRG_MAX(v) v = fmaxf(v, __shfl_xor_sync(0xffffffffu, v, 16))
    MRG_ADD(s.x); MRG_ADD(s.y); MRG_ADD(s.z); MRG_ADD(s.w);
    MRG_ADD(n.x); MRG_ADD(n.y); MRG_ADD(n.z); MRG_ADD(n.w);
    MRG_MIN(mn.x); MRG_MIN(mn.y); MRG_MIN(mn.z); MRG_MIN(mn.w);
    MRG_MAX(mx.x); MRG_MAX(mx.y); MRG_MAX(mx.z); MRG_MAX(mx.w);

    float4 a;
    a.x = (s.x > 0.f) ? n.x / s.x : 0.f;
    a.y = (s.y > 0.f) ? n.y / s.y : 0.f;
    a.z = (s.z > 0.f) ? n.z / s.z : 0.f;
    a.w = (s.w > 0.f) ? n.w / s.w : 0.f;

    float ss = a.x * a.x + a.y * a.y + a.z * a.z + a.w * a.w;
#pragma unroll
    for (int of = 8; of; of >>= 1) ss += __shfl_xor_sync(0xffffffffu, ss, of);
    float inv = 1.f / fmaxf(sqrtf(ss), 1e-12f);
    a.x *= inv; a.y *= inv; a.z *= inv; a.w *= inv;

    float4 ov;
    if (is_user) {
        float i0 = isinf(mn.x) ? 0.f : mn.x;
        float i1 = isinf(mn.y) ? 0.f : mn.y;
        float i2 = isinf(mn.z) ? 0.f : mn.z;
        float i3 = isinf(mn.w) ? 0.f : mn.w;
        ov = make_float4(fminf(i0, mx.x), fminf(i1, mx.y), fminf(i2, mx.z), fminf(i3, mx.w));
    } else if (is_item) {
        ov = mx;
    } else {
        ov.x = isinf(mn.x) ? 0.f : mn.x;
        ov.y = isinf(mn.y) ? 0.f : mn.y;
        ov.z = isinf(mn.z) ? 0.f : mn.z;
        ov.w = isinf(mn.w) ? 0.f : mn.w;
    }
    ov.x = fmaxf(ov.x, 0.f); ov.y = fmaxf(ov.y, 0.f);
    ov.z = fmaxf(ov.z, 0.f); ov.w = fmaxf(ov.w, 0.f);

    if (FINAL == 0) {
        size_t base = (size_t)w * 64 + fl;
        if (half == 0) *(float4*)(g_embsB + base) = a;
        else           *(float4*)(g_offB + base)  = ov;
    } else {
        size_t eb, ob;
        if (is_user) {
            eb = (size_t)w * 64;
            ob = (size_t)NU * 64 + (size_t)w * 64;
        } else if (is_item) {
            size_t b2 = (size_t)2 * NU * 64;
            eb = b2 + (size_t)(w - NU) * 64;
            ob = b2 + (size_t)NI * 64 + (size_t)(w - NU) * 64;
        } else {
            size_t b3 = (size_t)2 * (NU + NI) * 64;
            eb = b3 + (size_t)(w - NU - NI) * 64;
            ob = b3 + (size_t)NT * 64 + (size_t)(w - NU - NI) * 64;
        }
        if (half == 0) *(float4*)(out + eb + fl) = a;
        else           *(float4*)(out + ob + fl) = ov;
    }
}

// ---------------- launch ----------------
extern "C" void kernel_launch(void* const* d_in, const int* in_sizes, int n_in,
                              void* d_out, int out_size) {
    const float* user_emb = (const float*)d_in[0];
    const float* user_off = (const float*)d_in[1];
    const float* item_emb = (const float*)d_in[2];
    const float* item_off = (const float*)d_in[3];
    const float* tag_emb  = (const float*)d_in[4];
    const float* tag_off  = (const float*)d_in[5];
    const float* W1 = (const float*)d_in[6];
    const float* b1 = (const float*)d_in[7];
    const float* W2 = (const float*)d_in[8];
    const float* b2 = (const float*)d_in[9];
    const int* head = (const int*)d_in[10];
    const int* tail = (const int*)d_in[11];
    float* out = (float*)d_out;

    const int NB = (NNODES + SCAN_B - 1) / SCAN_B;

    // slot #4 (ncu capture) = mlp<0>; CSR chain completes before aggregate<0>
    zero_deg_kernel<<<(NNODES + 255) / 256, 256>>>(); // 1
    hist_kernel<<<(NE + 255) / 256, 256>>>(head);     // 2
    scan_block_kernel<<<NB, SCAN_B>>>();              // 3
    mlp_kernel<0><<<NNODES / 128, 128>>>(user_emb, item_emb, tag_emb,
                                         W1, b1, W2, b2);  // 4 <- profiled
    scan_sums_kernel<<<1, 256>>>(NB);                 // 5
    scan_add_kernel<<<NB, SCAN_B>>>();                // 6
    scatter_kernel<<<(NE + 255) / 256, 256>>>(head, tail);  // 7
    aggregate_kernel<0><<<(NNODES + 7) / 8, 256>>>(
        user_off, item_off, tag_off, out);            // 8
    mlp_kernel<1><<<NNODES / 128, 128>>>(user_emb, item_emb, tag_emb,
                                         W1, b1, W2, b2);  // 9
    aggregate_kernel<1><<<(NNODES + 7) / 8, 256>>>(
        user_off, item_off, tag_off, out);            // 10
}